// round 2
// baseline (speedup 1.0000x reference)
#include <cuda_runtime.h>

// Problem constants
#define VOCAB 30000
#define DIM   512
#define FEAT  256
#define SEQL  128
#define NSEQ  1024          // B*S = 16*64
#define NTAP  12            // 3 + 4 + 5
#define NCOL  3072          // NTAP * FEAT

// Scratch (module-load allocated; no runtime allocs)
__device__ float g_Wt[DIM * NCOL];                    // packed weights [D][3072]
__device__ float g_proj[(size_t)VOCAB * NCOL];        // per-vocab projections (368 MB)

// ---------------------------------------------------------------------------
// Kernel 1: pack w3/w4/w5 into Wt[d][n], n = tap*256 + f
//   taps 0..2 -> w3 k=0..2 ; taps 3..6 -> w4 k=0..3 ; taps 7..11 -> w5 k=0..4
// ---------------------------------------------------------------------------
__global__ void pack_weights(const float* __restrict__ w3,
                             const float* __restrict__ w4,
                             const float* __restrict__ w5) {
    int idx = blockIdx.x * blockDim.x + threadIdx.x;
    if (idx >= DIM * NCOL) return;
    int d = idx / NCOL;
    int n = idx % NCOL;
    int tap = n >> 8;
    int f   = n & 255;
    float v;
    if (tap < 3)      v = w3[(f * DIM + d) * 3 + tap];
    else if (tap < 7) v = w4[(f * DIM + d) * 4 + (tap - 3)];
    else              v = w5[(f * DIM + d) * 5 + (tap - 7)];
    g_Wt[idx] = v;
}

// ---------------------------------------------------------------------------
// Kernel 2: SGEMM  g_proj[V x NCOL] = embed[V x DIM] @ g_Wt[DIM x NCOL]
// fp32 with packed fma.rn.f32x2 (2 FMA/instr -> full 128 FMA/cyc/SM rate)
// ---------------------------------------------------------------------------
#define BM 128
#define BN 128
#define BKK 16

__device__ __forceinline__ void ffma2(unsigned long long& d,
                                      unsigned long long a,
                                      unsigned long long b) {
    asm("fma.rn.f32x2 %0, %1, %2, %0;" : "+l"(d) : "l"(a), "l"(b));
}
__device__ __forceinline__ unsigned long long pack2(float x) {
    unsigned long long r;
    asm("mov.b64 %0, {%1, %1};" : "=l"(r) : "f"(x));
    return r;
}

__global__ __launch_bounds__(256, 2)
void gemm_proj(const float* __restrict__ A /* embed [VOCAB][DIM] */) {
    __shared__ float As[BKK][BM + 4];   // transposed, padded vs. bank conflicts
    __shared__ float Bs[BKK][BN];

    int tid = threadIdx.x;
    int tx  = tid & 15;                 // N direction (8 cols each)
    int ty  = tid >> 4;                 // M direction (8 rows each)
    int m0  = blockIdx.y * BM;
    int n0  = blockIdx.x * BN;

    // acc[i][j]: f32x2 pair along M: rows (ty*8+2i, ty*8+2i+1), col tx*8+j
    unsigned long long acc[4][8];
#pragma unroll
    for (int i = 0; i < 4; i++)
#pragma unroll
        for (int j = 0; j < 8; j++) acc[i][j] = 0ULL;

    for (int k0 = 0; k0 < DIM; k0 += BKK) {
        // --- load A tile (128 x 16) as float4 along K, store transposed ---
#pragma unroll
        for (int s = 0; s < 2; s++) {
            int lid = tid * 2 + s;
            int r   = lid >> 2;         // 0..127
            int c4  = lid & 3;          // 0..3
            int gr  = m0 + r;
            if (gr >= VOCAB) gr = VOCAB - 1;   // clamp (stores predicated later)
            float4 v = *reinterpret_cast<const float4*>(&A[gr * DIM + k0 + c4 * 4]);
            As[c4 * 4 + 0][r] = v.x;
            As[c4 * 4 + 1][r] = v.y;
            As[c4 * 4 + 2][r] = v.z;
            As[c4 * 4 + 3][r] = v.w;
        }
        // --- load B tile (16 x 128), row-major float4 ---
#pragma unroll
        for (int s = 0; s < 2; s++) {
            int lid = tid * 2 + s;
            int r   = lid >> 5;         // 0..15
            int c4  = lid & 31;         // 0..31
            *reinterpret_cast<float4*>(&Bs[r][c4 * 4]) =
                *reinterpret_cast<const float4*>(&g_Wt[(size_t)(k0 + r) * NCOL + n0 + c4 * 4]);
        }
        __syncthreads();

#pragma unroll
        for (int k = 0; k < BKK; k++) {
            // a: 8 consecutive M values = 4 packed pairs (8B aligned: pad=4 keeps stride%8==0)
            const unsigned long long* ap =
                reinterpret_cast<const unsigned long long*>(&As[k][ty * 8]);
            unsigned long long a0 = ap[0], a1 = ap[1], a2 = ap[2], a3 = ap[3];

            const float4* bp = reinterpret_cast<const float4*>(&Bs[k][tx * 8]);
            float4 b0 = bp[0], b1 = bp[1];
            unsigned long long bb[8];
            bb[0] = pack2(b0.x); bb[1] = pack2(b0.y); bb[2] = pack2(b0.z); bb[3] = pack2(b0.w);
            bb[4] = pack2(b1.x); bb[5] = pack2(b1.y); bb[6] = pack2(b1.z); bb[7] = pack2(b1.w);

#pragma unroll
            for (int j = 0; j < 8; j++) {
                ffma2(acc[0][j], a0, bb[j]);
                ffma2(acc[1][j], a1, bb[j]);
                ffma2(acc[2][j], a2, bb[j]);
                ffma2(acc[3][j], a3, bb[j]);
            }
        }
        __syncthreads();
    }

    // --- store: coalesced float4 per output row ---
#pragma unroll
    for (int i = 0; i < 4; i++) {
        int gm0 = m0 + ty * 8 + 2 * i;
        float2 p[8];
#pragma unroll
        for (int j = 0; j < 8; j++) p[j] = *reinterpret_cast<float2*>(&acc[i][j]);
        float4 lo0 = make_float4(p[0].x, p[1].x, p[2].x, p[3].x);
        float4 lo1 = make_float4(p[4].x, p[5].x, p[6].x, p[7].x);
        float4 hi0 = make_float4(p[0].y, p[1].y, p[2].y, p[3].y);
        float4 hi1 = make_float4(p[4].y, p[5].y, p[6].y, p[7].y);
        size_t base = (size_t)gm0 * NCOL + n0 + tx * 8;
        if (gm0 < VOCAB) {
            *reinterpret_cast<float4*>(&g_proj[base])     = lo0;
            *reinterpret_cast<float4*>(&g_proj[base + 4]) = lo1;
        }
        if (gm0 + 1 < VOCAB) {
            *reinterpret_cast<float4*>(&g_proj[base + NCOL])     = hi0;
            *reinterpret_cast<float4*>(&g_proj[base + NCOL + 4]) = hi1;
        }
    }
}

// ---------------------------------------------------------------------------
// Kernel 3: per-sequence sliding-window sum + max-over-time + bias + relu
// block = one sequence (1024 blocks), thread = one feature f (256 threads)
// ---------------------------------------------------------------------------
__global__ __launch_bounds__(256)
void pool_kernel(const int* __restrict__ text,
                 const float* __restrict__ b3,
                 const float* __restrict__ b4,
                 const float* __restrict__ b5,
                 float* __restrict__ out) {
    int seq = blockIdx.x;
    int f   = threadIdx.x;

    __shared__ int s_tok[SEQL];
    if (f < SEQL) s_tok[f] = text[seq * SEQL + f];
    __syncthreads();

    float m3 = -1e30f, m4 = -1e30f, m5 = -1e30f;
    // rolling partial sums (window start p-1, p-2, ...)
    float c3a = 0.f, c3b = 0.f;
    float c4a = 0.f, c4b = 0.f, c4c = 0.f;
    float c5a = 0.f, c5b = 0.f, c5c = 0.f, c5d = 0.f;

#pragma unroll 2
    for (int p = 0; p < SEQL; p++) {
        const float* row = g_proj + (size_t)s_tok[p] * NCOL + f;
        float t0  = row[0 * FEAT];
        float t1  = row[1 * FEAT];
        float t2  = row[2 * FEAT];
        float t3  = row[3 * FEAT];
        float t4  = row[4 * FEAT];
        float t5  = row[5 * FEAT];
        float t6  = row[6 * FEAT];
        float t7  = row[7 * FEAT];
        float t8  = row[8 * FEAT];
        float t9  = row[9 * FEAT];
        float t10 = row[10 * FEAT];
        float t11 = row[11 * FEAT];

        // K = 3 (taps t0..t2)
        if (p >= 2) m3 = fmaxf(m3, c3b + t2);
        c3b = c3a + t1;
        c3a = t0;
        // K = 4 (taps t3..t6)
        if (p >= 3) m4 = fmaxf(m4, c4c + t6);
        c4c = c4b + t5;
        c4b = c4a + t4;
        c4a = t3;
        // K = 5 (taps t7..t11)
        if (p >= 4) m5 = fmaxf(m5, c5d + t11);
        c5d = c5c + t10;
        c5c = c5b + t9;
        c5b = c5a + t8;
        c5a = t7;
    }

    float o3 = m3 + b3[f];
    float o4 = m4 + b4[f];
    float o5 = m5 + b5[f];
    float* o = out + (size_t)seq * (3 * FEAT);
    o[f]            = o3 > 0.f ? o3 : 0.f;
    o[FEAT + f]     = o4 > 0.f ? o4 : 0.f;
    o[2 * FEAT + f] = o5 > 0.f ? o5 : 0.f;
}

// ---------------------------------------------------------------------------
extern "C" void kernel_launch(void* const* d_in, const int* in_sizes, int n_in,
                              void* d_out, int out_size) {
    const int*   text  = (const int*)  d_in[0];
    const float* embed = (const float*)d_in[1];
    const float* w3    = (const float*)d_in[2];
    const float* b3    = (const float*)d_in[3];
    const float* w4    = (const float*)d_in[4];
    const float* b4    = (const float*)d_in[5];
    const float* w5    = (const float*)d_in[6];
    const float* b5    = (const float*)d_in[7];
    float* out = (float*)d_out;

    // 1) pack weights into [DIM][NCOL]
    {
        int total = DIM * NCOL;
        pack_weights<<<(total + 255) / 256, 256>>>(w3, w4, w5);
    }
    // 2) per-vocab projection GEMM: [VOCAB x DIM] @ [DIM x NCOL]
    {
        dim3 grid(NCOL / BN, (VOCAB + BM - 1) / BM);
        gemm_proj<<<grid, 256>>>(embed);
    }
    // 3) gather + sliding-window conv + max pool + bias + relu
    pool_kernel<<<NSEQ, 256>>>(text, b3, b4, b5, out);
}

// round 4
// speedup vs baseline: 2.3761x; 2.3761x over previous
#include <cuda_runtime.h>
#include <cuda_bf16.h>
#include <stdint.h>

// ---------------------------------------------------------------------------
// Problem constants
// ---------------------------------------------------------------------------
#define VOCAB 30000
#define DIM   512
#define FEAT  256
#define SEQL  128
#define NSEQ  1024          // B*S
#define NCOL  3072          // 12 taps * 256 feat

// ---------------------------------------------------------------------------
// Scratch
// ---------------------------------------------------------------------------
__device__ __align__(128) __nv_bfloat16 g_Ahi[(size_t)VOCAB * DIM];
__device__ __align__(128) __nv_bfloat16 g_Alo[(size_t)VOCAB * DIM];
__device__ __align__(128) __nv_bfloat16 g_Bhi[(size_t)NCOL * DIM];   // [n][k]
__device__ __align__(128) __nv_bfloat16 g_Blo[(size_t)NCOL * DIM];
__device__ __align__(128) float g_proj[(size_t)VOCAB * NCOL];

// ---------------------------------------------------------------------------
// PTX helpers (all portable PTX: sm_80-era, legal on compute_103)
// ---------------------------------------------------------------------------
static __device__ __forceinline__ uint32_t smem_u32(const void* p) {
    uint32_t a;
    asm("{ .reg .u64 t; cvta.to.shared.u64 t, %1; cvt.u32.u64 %0, t; }" : "=r"(a) : "l"(p));
    return a;
}
static __device__ __forceinline__ void cpa16(uint32_t s, const void* g) {
    asm volatile("cp.async.cg.shared.global [%0], [%1], 16;" :: "r"(s), "l"(g));
}
static __device__ __forceinline__ void cp_commit() {
    asm volatile("cp.async.commit_group;" ::: "memory");
}
template <int N> static __device__ __forceinline__ void cp_wait() {
    asm volatile("cp.async.wait_group %0;" :: "n"(N) : "memory");
}
static __device__ __forceinline__ void ldsm4(uint32_t& r0, uint32_t& r1,
                                             uint32_t& r2, uint32_t& r3, uint32_t a) {
    asm volatile("ldmatrix.sync.aligned.m8n8.x4.shared.b16 {%0,%1,%2,%3}, [%4];"
                 : "=r"(r0), "=r"(r1), "=r"(r2), "=r"(r3) : "r"(a));
}
static __device__ __forceinline__ void mma16816(float* d, const uint32_t* a,
                                                const uint32_t* b) {
    asm volatile(
        "mma.sync.aligned.m16n8k16.row.col.f32.bf16.bf16.f32 "
        "{%0,%1,%2,%3}, {%4,%5,%6,%7}, {%8,%9}, {%0,%1,%2,%3};"
        : "+f"(d[0]), "+f"(d[1]), "+f"(d[2]), "+f"(d[3])
        : "r"(a[0]), "r"(a[1]), "r"(a[2]), "r"(a[3]), "r"(b[0]), "r"(b[1]));
}

// ---------------------------------------------------------------------------
// Kernel 1: split embed into bf16 hi/lo
// ---------------------------------------------------------------------------
__global__ void convert_embed(const float* __restrict__ e) {
    size_t i = ((size_t)blockIdx.x * blockDim.x + threadIdx.x) * 8;
    if (i >= (size_t)VOCAB * DIM) return;
    float4 v0 = *reinterpret_cast<const float4*>(e + i);
    float4 v1 = *reinterpret_cast<const float4*>(e + i + 4);
    float x[8] = {v0.x, v0.y, v0.z, v0.w, v1.x, v1.y, v1.z, v1.w};
    __align__(16) __nv_bfloat16 hi[8], lo[8];
#pragma unroll
    for (int j = 0; j < 8; j++) {
        hi[j] = __float2bfloat16(x[j]);
        lo[j] = __float2bfloat16(x[j] - __bfloat162float(hi[j]));
    }
    *reinterpret_cast<uint4*>(&g_Ahi[i]) = *reinterpret_cast<uint4*>(hi);
    *reinterpret_cast<uint4*>(&g_Alo[i]) = *reinterpret_cast<uint4*>(lo);
}

// ---------------------------------------------------------------------------
// Kernel 2: pack + split weights: B[n][k], n = tap*256+f
// ---------------------------------------------------------------------------
__global__ void pack_w(const float* __restrict__ w3,
                       const float* __restrict__ w4,
                       const float* __restrict__ w5) {
    int idx = blockIdx.x * blockDim.x + threadIdx.x;
    if (idx >= NCOL * DIM) return;
    int n = idx >> 9;
    int k = idx & 511;
    int tap = n >> 8;
    int f   = n & 255;
    float v;
    if (tap < 3)      v = w3[(f * DIM + k) * 3 + tap];
    else if (tap < 7) v = w4[(f * DIM + k) * 4 + (tap - 3)];
    else              v = w5[(f * DIM + k) * 5 + (tap - 7)];
    __nv_bfloat16 hi = __float2bfloat16(v);
    __nv_bfloat16 lo = __float2bfloat16(v - __bfloat162float(hi));
    g_Bhi[idx] = hi;
    g_Blo[idx] = lo;
}

// ---------------------------------------------------------------------------
// Kernel 3: mma.sync bf16 GEMM, 3-term split, K_eff = 1536
//   CTA tile 128x256, BK=64 halves, 3-stage cp.async pipeline, 8 warps 64x64
// ---------------------------------------------------------------------------
#define BM 128
#define BN 256
#define BKH 64
#define STAGES 3
#define ASTG 16384                // 128 rows * 128B
#define BSTG 32768                // 256 rows * 128B
#define STG (ASTG + BSTG)         // 48KB / stage
#define NIT 24                    // 3 passes * 8 K-stages
#define GEMM_SMEM (STAGES * STG + 1024)

__global__ __launch_bounds__(256, 1) void gemm_bf16() {
    extern __shared__ char dyn[];
    uint32_t base = (smem_u32(dyn) + 1023) & ~1023u;

    int tid  = threadIdx.x;
    int lane = tid & 31;
    int warp = tid >> 5;
    int wm = warp >> 2;            // 0..1  (64 rows each)
    int wn = warp & 3;             // 0..3  (64 cols each)
    int m0 = blockIdx.y * BM;
    int n0 = blockIdx.x * BN;

    // ---- per-thread ldmatrix source rows (fixed across stages) ----
    // A: row = wm*64 + mt*16 + (lane&15), chunk-bit = lane>>4
    int aRow[4], aXor[4];
#pragma unroll
    for (int mt = 0; mt < 4; mt++) {
        int r = wm * 64 + mt * 16 + (lane & 15);
        aRow[mt] = r * 128;
        aXor[mt] = r & 7;
    }
    int aCb = lane >> 4;
    // B: row = wn*64 + ntp*16 + (lane&7) + ((lane>>4)<<3), chunk-bit = (lane>>3)&1
    int bRow[4], bXor[4];
#pragma unroll
    for (int ntp = 0; ntp < 4; ntp++) {
        int r = wn * 64 + ntp * 16 + (lane & 7) + ((lane >> 4) << 3);
        bRow[ntp] = r * 128;
        bXor[ntp] = r & 7;
    }
    int bCb = (lane >> 3) & 1;

    float acc[4][8][4];
#pragma unroll
    for (int mt = 0; mt < 4; mt++)
#pragma unroll
        for (int nt = 0; nt < 8; nt++)
#pragma unroll
            for (int q = 0; q < 4; q++) acc[mt][nt][q] = 0.f;

    auto load_stage = [&](int g) {
        int pass = g >> 3;
        int k0   = (g & 7) * BKH;
        const __nv_bfloat16* Ab = (pass == 1) ? g_Alo : g_Ahi;
        const __nv_bfloat16* Bb = (pass == 2) ? g_Blo : g_Bhi;
        uint32_t sA = base + (g % STAGES) * STG;
        uint32_t sB = sA + ASTG;
#pragma unroll
        for (int j = 0; j < 4; j++) {               // A: 1024 chunks
            int c = tid + 256 * j;
            int r = c >> 3, q = c & 7;
            int grow = m0 + r; if (grow >= VOCAB) grow = VOCAB - 1;
            uint32_t off = (uint32_t)(r * 128 + ((q ^ (r & 7)) << 4));
            cpa16(sA + off, Ab + (size_t)grow * DIM + k0 + q * 8);
        }
#pragma unroll
        for (int j = 0; j < 8; j++) {               // B: 2048 chunks
            int c = tid + 256 * j;
            int r = c >> 3, q = c & 7;
            uint32_t off = (uint32_t)(r * 128 + ((q ^ (r & 7)) << 4));
            cpa16(sB + off, Bb + (size_t)(n0 + r) * DIM + k0 + q * 8);
        }
        cp_commit();
    };

    load_stage(0);
    load_stage(1);

    for (int i = 0; i < NIT; i++) {
        if (i == NIT - 1) cp_wait<0>(); else cp_wait<1>();
        __syncthreads();

        if (i + 2 < NIT) load_stage(i + 2);

        uint32_t sA = base + (i % STAGES) * STG;
        uint32_t sB = sA + ASTG;
#pragma unroll
        for (int s = 0; s < 4; s++) {               // 4 k16 steps per stage
            uint32_t a[4][4], b[8][2];
#pragma unroll
            for (int mt = 0; mt < 4; mt++) {
                uint32_t addr = sA + aRow[mt] + ((uint32_t)((2 * s + aCb) ^ aXor[mt]) << 4);
                ldsm4(a[mt][0], a[mt][1], a[mt][2], a[mt][3], addr);
            }
#pragma unroll
            for (int ntp = 0; ntp < 4; ntp++) {
                uint32_t addr = sB + bRow[ntp] + ((uint32_t)((2 * s + bCb) ^ bXor[ntp]) << 4);
                ldsm4(b[2 * ntp][0], b[2 * ntp][1], b[2 * ntp + 1][0], b[2 * ntp + 1][1], addr);
            }
#pragma unroll
            for (int mt = 0; mt < 4; mt++)
#pragma unroll
                for (int nt = 0; nt < 8; nt++)
                    mma16816(acc[mt][nt], a[mt], b[nt]);
        }
        __syncthreads();
    }

    // ---- epilogue: direct float2 stores ----
#pragma unroll
    for (int mt = 0; mt < 4; mt++) {
        int r0 = m0 + wm * 64 + mt * 16 + (lane >> 2);
        int r1 = r0 + 8;
        float* p0 = g_proj + (size_t)r0 * NCOL + n0 + wn * 64 + (lane & 3) * 2;
        float* p1 = g_proj + (size_t)r1 * NCOL + n0 + wn * 64 + (lane & 3) * 2;
        bool ok0 = r0 < VOCAB, ok1 = r1 < VOCAB;
#pragma unroll
        for (int nt = 0; nt < 8; nt++) {
            if (ok0) *reinterpret_cast<float2*>(p0 + nt * 8) =
                make_float2(acc[mt][nt][0], acc[mt][nt][1]);
            if (ok1) *reinterpret_cast<float2*>(p1 + nt * 8) =
                make_float2(acc[mt][nt][2], acc[mt][nt][3]);
        }
    }
}

// ---------------------------------------------------------------------------
// Kernel 4: per-sequence sliding-window sum + max-over-time + bias + relu
// ---------------------------------------------------------------------------
__global__ __launch_bounds__(256)
void pool_kernel(const int* __restrict__ text,
                 const float* __restrict__ b3,
                 const float* __restrict__ b4,
                 const float* __restrict__ b5,
                 float* __restrict__ out) {
    int seq = blockIdx.x;
    int f   = threadIdx.x;

    __shared__ int s_tok[SEQL];
    if (f < SEQL) s_tok[f] = text[seq * SEQL + f];
    __syncthreads();

    float m3 = -1e30f, m4 = -1e30f, m5 = -1e30f;
    float c3a = 0.f, c3b = 0.f;
    float c4a = 0.f, c4b = 0.f, c4c = 0.f;
    float c5a = 0.f, c5b = 0.f, c5c = 0.f, c5d = 0.f;

#pragma unroll 2
    for (int p = 0; p < SEQL; p++) {
        const float* row = g_proj + (size_t)s_tok[p] * NCOL + f;
        float t0  = row[0 * FEAT];
        float t1  = row[1 * FEAT];
        float t2  = row[2 * FEAT];
        float t3  = row[3 * FEAT];
        float t4  = row[4 * FEAT];
        float t5  = row[5 * FEAT];
        float t6  = row[6 * FEAT];
        float t7  = row[7 * FEAT];
        float t8  = row[8 * FEAT];
        float t9  = row[9 * FEAT];
        float t10 = row[10 * FEAT];
        float t11 = row[11 * FEAT];

        if (p >= 2) m3 = fmaxf(m3, c3b + t2);
        c3b = c3a + t1;  c3a = t0;
        if (p >= 3) m4 = fmaxf(m4, c4c + t6);
        c4c = c4b + t5;  c4b = c4a + t4;  c4a = t3;
        if (p >= 4) m5 = fmaxf(m5, c5d + t11);
        c5d = c5c + t10; c5c = c5b + t9;  c5b = c5a + t8;  c5a = t7;
    }

    float o3 = m3 + b3[f];
    float o4 = m4 + b4[f];
    float o5 = m5 + b5[f];
    float* o = out + (size_t)seq * (3 * FEAT);
    o[f]            = o3 > 0.f ? o3 : 0.f;
    o[FEAT + f]     = o4 > 0.f ? o4 : 0.f;
    o[2 * FEAT + f] = o5 > 0.f ? o5 : 0.f;
}

// ---------------------------------------------------------------------------
extern "C" void kernel_launch(void* const* d_in, const int* in_sizes, int n_in,
                              void* d_out, int out_size) {
    const int*   text  = (const int*)  d_in[0];
    const float* embed = (const float*)d_in[1];
    const float* w3    = (const float*)d_in[2];
    const float* b3    = (const float*)d_in[3];
    const float* w4    = (const float*)d_in[4];
    const float* b4    = (const float*)d_in[5];
    const float* w5    = (const float*)d_in[6];
    const float* b5    = (const float*)d_in[7];
    float* out = (float*)d_out;

    convert_embed<<<(VOCAB * DIM / 8 + 255) / 256, 256>>>(embed);
    pack_w<<<(NCOL * DIM + 255) / 256, 256>>>(w3, w4, w5);

    cudaFuncSetAttribute(gemm_bf16, cudaFuncAttributeMaxDynamicSharedMemorySize, GEMM_SMEM);
    gemm_bf16<<<dim3(NCOL / BN, (VOCAB + BM - 1) / BM), 256, GEMM_SMEM>>>();

    pool_kernel<<<NSEQ, 256>>>(text, b3, b4, b5, out);
}

// round 5
// speedup vs baseline: 4.8478x; 2.0403x over previous
#include <cuda_runtime.h>
#include <cuda_fp16.h>
#include <stdint.h>

// ---------------------------------------------------------------------------
// Problem constants
// ---------------------------------------------------------------------------
#define VOCAB 30000
#define DIM   512
#define FEAT  256
#define SEQL  128
#define NSEQ  1024          // B*S
#define NCOL  3072          // 12 taps * 256 feat

// ---------------------------------------------------------------------------
// Scratch (all fp16 now: single-pass GEMM, fp16 projection table)
// ---------------------------------------------------------------------------
__device__ __align__(128) __half g_Ah[(size_t)VOCAB * DIM];
__device__ __align__(128) __half g_Bh[(size_t)NCOL * DIM];     // [n][k]
__device__ __align__(128) __half g_proj[(size_t)VOCAB * NCOL]; // 184 MB

// ---------------------------------------------------------------------------
// PTX helpers (portable sm_80-era PTX, legal on compute_103)
// ---------------------------------------------------------------------------
static __device__ __forceinline__ uint32_t smem_u32(const void* p) {
    uint32_t a;
    asm("{ .reg .u64 t; cvta.to.shared.u64 t, %1; cvt.u32.u64 %0, t; }" : "=r"(a) : "l"(p));
    return a;
}
static __device__ __forceinline__ void cpa16(uint32_t s, const void* g) {
    asm volatile("cp.async.cg.shared.global [%0], [%1], 16;" :: "r"(s), "l"(g));
}
static __device__ __forceinline__ void cp_commit() {
    asm volatile("cp.async.commit_group;" ::: "memory");
}
template <int N> static __device__ __forceinline__ void cp_wait() {
    asm volatile("cp.async.wait_group %0;" :: "n"(N) : "memory");
}
static __device__ __forceinline__ void ldsm4(uint32_t& r0, uint32_t& r1,
                                             uint32_t& r2, uint32_t& r3, uint32_t a) {
    asm volatile("ldmatrix.sync.aligned.m8n8.x4.shared.b16 {%0,%1,%2,%3}, [%4];"
                 : "=r"(r0), "=r"(r1), "=r"(r2), "=r"(r3) : "r"(a));
}
static __device__ __forceinline__ void mma16816(float* d, const uint32_t* a,
                                                const uint32_t* b) {
    asm volatile(
        "mma.sync.aligned.m16n8k16.row.col.f32.f16.f16.f32 "
        "{%0,%1,%2,%3}, {%4,%5,%6,%7}, {%8,%9}, {%0,%1,%2,%3};"
        : "+f"(d[0]), "+f"(d[1]), "+f"(d[2]), "+f"(d[3])
        : "r"(a[0]), "r"(a[1]), "r"(a[2]), "r"(a[3]), "r"(b[0]), "r"(b[1]));
}

// ---------------------------------------------------------------------------
// Kernel 1: embed fp32 -> fp16
// ---------------------------------------------------------------------------
__global__ void convert_embed(const float* __restrict__ e) {
    size_t i = ((size_t)blockIdx.x * blockDim.x + threadIdx.x) * 8;
    if (i >= (size_t)VOCAB * DIM) return;
    float4 v0 = *reinterpret_cast<const float4*>(e + i);
    float4 v1 = *reinterpret_cast<const float4*>(e + i + 4);
    __align__(16) __half h[8];
    h[0] = __float2half_rn(v0.x); h[1] = __float2half_rn(v0.y);
    h[2] = __float2half_rn(v0.z); h[3] = __float2half_rn(v0.w);
    h[4] = __float2half_rn(v1.x); h[5] = __float2half_rn(v1.y);
    h[6] = __float2half_rn(v1.z); h[7] = __float2half_rn(v1.w);
    *reinterpret_cast<uint4*>(&g_Ah[i]) = *reinterpret_cast<uint4*>(h);
}

// ---------------------------------------------------------------------------
// Kernel 2: pack weights: B[n][k], n = tap*256+f
// ---------------------------------------------------------------------------
__global__ void pack_w(const float* __restrict__ w3,
                       const float* __restrict__ w4,
                       const float* __restrict__ w5) {
    int idx = blockIdx.x * blockDim.x + threadIdx.x;
    if (idx >= NCOL * DIM) return;
    int n = idx >> 9;
    int k = idx & 511;
    int tap = n >> 8;
    int f   = n & 255;
    float v;
    if (tap < 3)      v = w3[(f * DIM + k) * 3 + tap];
    else if (tap < 7) v = w4[(f * DIM + k) * 4 + (tap - 3)];
    else              v = w5[(f * DIM + k) * 5 + (tap - 7)];
    g_Bh[idx] = __float2half_rn(v);
}

// ---------------------------------------------------------------------------
// Kernel 3: single-pass fp16 mma.sync GEMM, K = 512
//   CTA tile 128x256, BK=64, 3-stage cp.async pipeline, 8 warps @ 64x64
// ---------------------------------------------------------------------------
#define BM 128
#define BN 256
#define BKH 64
#define STAGES 3
#define ASTG 16384                // 128 rows * 128B
#define BSTG 32768                // 256 rows * 128B
#define STG (ASTG + BSTG)         // 48KB / stage
#define NIT 8                     // 512 / 64
#define GEMM_SMEM (STAGES * STG + 1024)

__global__ __launch_bounds__(256, 1) void gemm_f16() {
    extern __shared__ char dyn[];
    uint32_t base = (smem_u32(dyn) + 1023) & ~1023u;

    int tid  = threadIdx.x;
    int lane = tid & 31;
    int warp = tid >> 5;
    int wm = warp >> 2;            // 0..1  (64 rows each)
    int wn = warp & 3;             // 0..3  (64 cols each)
    int m0 = blockIdx.y * BM;
    int n0 = blockIdx.x * BN;

    // ---- per-thread ldmatrix source rows ----
    int aRow[4], aXor[4];
#pragma unroll
    for (int mt = 0; mt < 4; mt++) {
        int r = wm * 64 + mt * 16 + (lane & 15);
        aRow[mt] = r * 128;
        aXor[mt] = r & 7;
    }
    int aCb = lane >> 4;
    int bRow[4], bXor[4];
#pragma unroll
    for (int ntp = 0; ntp < 4; ntp++) {
        int r = wn * 64 + ntp * 16 + (lane & 7) + ((lane >> 4) << 3);
        bRow[ntp] = r * 128;
        bXor[ntp] = r & 7;
    }
    int bCb = (lane >> 3) & 1;

    float acc[4][8][4];
#pragma unroll
    for (int mt = 0; mt < 4; mt++)
#pragma unroll
        for (int nt = 0; nt < 8; nt++)
#pragma unroll
            for (int q = 0; q < 4; q++) acc[mt][nt][q] = 0.f;

    auto load_stage = [&](int g) {
        int k0 = g * BKH;
        uint32_t sA = base + (g % STAGES) * STG;
        uint32_t sB = sA + ASTG;
#pragma unroll
        for (int j = 0; j < 4; j++) {               // A: 1024 16B chunks
            int c = tid + 256 * j;
            int r = c >> 3, q = c & 7;
            int grow = m0 + r; if (grow >= VOCAB) grow = VOCAB - 1;
            uint32_t off = (uint32_t)(r * 128 + ((q ^ (r & 7)) << 4));
            cpa16(sA + off, g_Ah + (size_t)grow * DIM + k0 + q * 8);
        }
#pragma unroll
        for (int j = 0; j < 8; j++) {               // B: 2048 16B chunks
            int c = tid + 256 * j;
            int r = c >> 3, q = c & 7;
            uint32_t off = (uint32_t)(r * 128 + ((q ^ (r & 7)) << 4));
            cpa16(sB + off, g_Bh + (size_t)(n0 + r) * DIM + k0 + q * 8);
        }
        cp_commit();
    };

    load_stage(0);
    load_stage(1);

    for (int i = 0; i < NIT; i++) {
        if (i == NIT - 1) cp_wait<0>(); else cp_wait<1>();
        __syncthreads();

        if (i + 2 < NIT) load_stage(i + 2);

        uint32_t sA = base + (i % STAGES) * STG;
        uint32_t sB = sA + ASTG;
#pragma unroll
        for (int s = 0; s < 4; s++) {               // 4 k16 steps per stage
            uint32_t a[4][4], b[8][2];
#pragma unroll
            for (int mt = 0; mt < 4; mt++) {
                uint32_t addr = sA + aRow[mt] + ((uint32_t)((2 * s + aCb) ^ aXor[mt]) << 4);
                ldsm4(a[mt][0], a[mt][1], a[mt][2], a[mt][3], addr);
            }
#pragma unroll
            for (int ntp = 0; ntp < 4; ntp++) {
                uint32_t addr = sB + bRow[ntp] + ((uint32_t)((2 * s + bCb) ^ bXor[ntp]) << 4);
                ldsm4(b[2 * ntp][0], b[2 * ntp][1], b[2 * ntp + 1][0], b[2 * ntp + 1][1], addr);
            }
#pragma unroll
            for (int mt = 0; mt < 4; mt++)
#pragma unroll
                for (int nt = 0; nt < 8; nt++)
                    mma16816(acc[mt][nt], a[mt], b[nt]);
        }
        __syncthreads();
    }

    // ---- epilogue: fp16 stores (half2, 4B aligned) ----
#pragma unroll
    for (int mt = 0; mt < 4; mt++) {
        int r0 = m0 + wm * 64 + mt * 16 + (lane >> 2);
        int r1 = r0 + 8;
        __half* p0 = g_proj + (size_t)r0 * NCOL + n0 + wn * 64 + (lane & 3) * 2;
        __half* p1 = g_proj + (size_t)r1 * NCOL + n0 + wn * 64 + (lane & 3) * 2;
        bool ok0 = r0 < VOCAB, ok1 = r1 < VOCAB;
#pragma unroll
        for (int nt = 0; nt < 8; nt++) {
            if (ok0) *reinterpret_cast<__half2*>(p0 + nt * 8) =
                __floats2half2_rn(acc[mt][nt][0], acc[mt][nt][1]);
            if (ok1) *reinterpret_cast<__half2*>(p1 + nt * 8) =
                __floats2half2_rn(acc[mt][nt][2], acc[mt][nt][3]);
        }
    }
}

// ---------------------------------------------------------------------------
// Kernel 4: per-sequence sliding-window sum + max-over-time + bias + relu
// ---------------------------------------------------------------------------
__global__ __launch_bounds__(256)
void pool_kernel(const int* __restrict__ text,
                 const float* __restrict__ b3,
                 const float* __restrict__ b4,
                 const float* __restrict__ b5,
                 float* __restrict__ out) {
    int seq = blockIdx.x;
    int f   = threadIdx.x;

    __shared__ int s_tok[SEQL];
    if (f < SEQL) s_tok[f] = text[seq * SEQL + f];
    __syncthreads();

    float m3 = -1e30f, m4 = -1e30f, m5 = -1e30f;
    float c3a = 0.f, c3b = 0.f;
    float c4a = 0.f, c4b = 0.f, c4c = 0.f;
    float c5a = 0.f, c5b = 0.f, c5c = 0.f, c5d = 0.f;

#pragma unroll 2
    for (int p = 0; p < SEQL; p++) {
        const __half* row = g_proj + (size_t)s_tok[p] * NCOL + f;
        float t0  = __half2float(row[0 * FEAT]);
        float t1  = __half2float(row[1 * FEAT]);
        float t2  = __half2float(row[2 * FEAT]);
        float t3  = __half2float(row[3 * FEAT]);
        float t4  = __half2float(row[4 * FEAT]);
        float t5  = __half2float(row[5 * FEAT]);
        float t6  = __half2float(row[6 * FEAT]);
        float t7  = __half2float(row[7 * FEAT]);
        float t8  = __half2float(row[8 * FEAT]);
        float t9  = __half2float(row[9 * FEAT]);
        float t10 = __half2float(row[10 * FEAT]);
        float t11 = __half2float(row[11 * FEAT]);

        if (p >= 2) m3 = fmaxf(m3, c3b + t2);
        c3b = c3a + t1;  c3a = t0;
        if (p >= 3) m4 = fmaxf(m4, c4c + t6);
        c4c = c4b + t5;  c4b = c4a + t4;  c4a = t3;
        if (p >= 4) m5 = fmaxf(m5, c5d + t11);
        c5d = c5c + t10; c5c = c5b + t9;  c5b = c5a + t8;  c5a = t7;
    }

    float o3 = m3 + b3[f];
    float o4 = m4 + b4[f];
    float o5 = m5 + b5[f];
    float* o = out + (size_t)seq * (3 * FEAT);
    o[f]            = o3 > 0.f ? o3 : 0.f;
    o[FEAT + f]     = o4 > 0.f ? o4 : 0.f;
    o[2 * FEAT + f] = o5 > 0.f ? o5 : 0.f;
}

// ---------------------------------------------------------------------------
extern "C" void kernel_launch(void* const* d_in, const int* in_sizes, int n_in,
                              void* d_out, int out_size) {
    const int*   text  = (const int*)  d_in[0];
    const float* embed = (const float*)d_in[1];
    const float* w3    = (const float*)d_in[2];
    const float* b3    = (const float*)d_in[3];
    const float* w4    = (const float*)d_in[4];
    const float* b4    = (const float*)d_in[5];
    const float* w5    = (const float*)d_in[6];
    const float* b5    = (const float*)d_in[7];
    float* out = (float*)d_out;

    convert_embed<<<(VOCAB * DIM / 8 + 255) / 256, 256>>>(embed);
    pack_w<<<(NCOL * DIM + 255) / 256, 256>>>(w3, w4, w5);

    cudaFuncSetAttribute(gemm_f16, cudaFuncAttributeMaxDynamicSharedMemorySize, GEMM_SMEM);
    gemm_f16<<<dim3(NCOL / BN, (VOCAB + BM - 1) / BM), 256, GEMM_SMEM>>>();

    pool_kernel<<<NSEQ, 256>>>(text, b3, b4, b5, out);
}

// round 6
// speedup vs baseline: 5.4620x; 1.1267x over previous
#include <cuda_runtime.h>
#include <cuda_fp16.h>
#include <stdint.h>

// ---------------------------------------------------------------------------
#define VOCAB 30000
#define DIM   512
#define FEAT  256
#define SEQL  128
#define NSEQ  1024
#define NCOL  3072

__device__ __align__(128) __half g_Ah[(size_t)VOCAB * DIM];
__device__ __align__(128) __half g_Bh[(size_t)NCOL * DIM];
__device__ __align__(128) __half g_proj[(size_t)VOCAB * NCOL];

// ---------------------------------------------------------------------------
static __device__ __forceinline__ uint32_t smem_u32(const void* p) {
    uint32_t a;
    asm("{ .reg .u64 t; cvta.to.shared.u64 t, %1; cvt.u32.u64 %0, t; }" : "=r"(a) : "l"(p));
    return a;
}
static __device__ __forceinline__ void cpa16(uint32_t s, const void* g) {
    asm volatile("cp.async.cg.shared.global [%0], [%1], 16;" :: "r"(s), "l"(g));
}
static __device__ __forceinline__ void cp_commit() {
    asm volatile("cp.async.commit_group;" ::: "memory");
}
template <int N> static __device__ __forceinline__ void cp_wait() {
    asm volatile("cp.async.wait_group %0;" :: "n"(N) : "memory");
}
static __device__ __forceinline__ void ldsm4(uint32_t& r0, uint32_t& r1,
                                             uint32_t& r2, uint32_t& r3, uint32_t a) {
    asm volatile("ldmatrix.sync.aligned.m8n8.x4.shared.b16 {%0,%1,%2,%3}, [%4];"
                 : "=r"(r0), "=r"(r1), "=r"(r2), "=r"(r3) : "r"(a));
}
static __device__ __forceinline__ void mma16816(float* d, const uint32_t* a,
                                                const uint32_t* b) {
    asm volatile(
        "mma.sync.aligned.m16n8k16.row.col.f32.f16.f16.f32 "
        "{%0,%1,%2,%3}, {%4,%5,%6,%7}, {%8,%9}, {%0,%1,%2,%3};"
        : "+f"(d[0]), "+f"(d[1]), "+f"(d[2]), "+f"(d[3])
        : "r"(a[0]), "r"(a[1]), "r"(a[2]), "r"(a[3]), "r"(b[0]), "r"(b[1]));
}
static __device__ __forceinline__ float2 add2(float2 a, float2 b) {
    return make_float2(a.x + b.x, a.y + b.y);
}
static __device__ __forceinline__ float2 max2(float2 a, float2 b) {
    return make_float2(fmaxf(a.x, b.x), fmaxf(a.y, b.y));
}

// ---------------------------------------------------------------------------
// Kernel 1: embed fp32 -> fp16
// ---------------------------------------------------------------------------
__global__ void convert_embed(const float* __restrict__ e) {
    size_t i = ((size_t)blockIdx.x * blockDim.x + threadIdx.x) * 8;
    if (i >= (size_t)VOCAB * DIM) return;
    float4 v0 = *reinterpret_cast<const float4*>(e + i);
    float4 v1 = *reinterpret_cast<const float4*>(e + i + 4);
    __align__(16) __half h[8];
    h[0] = __float2half_rn(v0.x); h[1] = __float2half_rn(v0.y);
    h[2] = __float2half_rn(v0.z); h[3] = __float2half_rn(v0.w);
    h[4] = __float2half_rn(v1.x); h[5] = __float2half_rn(v1.y);
    h[6] = __float2half_rn(v1.z); h[7] = __float2half_rn(v1.w);
    *reinterpret_cast<uint4*>(&g_Ah[i]) = *reinterpret_cast<uint4*>(h);
}

// ---------------------------------------------------------------------------
// Kernel 2: pack weights B[n][k], n = tap*256+f
// ---------------------------------------------------------------------------
__global__ void pack_w(const float* __restrict__ w3,
                       const float* __restrict__ w4,
                       const float* __restrict__ w5) {
    int idx = blockIdx.x * blockDim.x + threadIdx.x;
    if (idx >= NCOL * DIM) return;
    int n = idx >> 9;
    int k = idx & 511;
    int tap = n >> 8;
    int f   = n & 255;
    float v;
    if (tap < 3)      v = w3[(f * DIM + k) * 3 + tap];
    else if (tap < 7) v = w4[(f * DIM + k) * 4 + (tap - 3)];
    else              v = w5[(f * DIM + k) * 5 + (tap - 7)];
    g_Bh[idx] = __float2half_rn(v);
}

// ---------------------------------------------------------------------------
// Kernel 3: fp16 mma.sync GEMM, K=512, frag double-buffered
// ---------------------------------------------------------------------------
#define BM 128
#define BN 256
#define BKH 64
#define STAGES 3
#define ASTG 16384
#define BSTG 32768
#define STG (ASTG + BSTG)
#define NIT 8
#define GEMM_SMEM (STAGES * STG + 1024)

__global__ __launch_bounds__(256, 1) void gemm_f16() {
    extern __shared__ char dyn[];
    uint32_t base = (smem_u32(dyn) + 1023) & ~1023u;

    int tid  = threadIdx.x;
    int lane = tid & 31;
    int warp = tid >> 5;
    int wm = warp >> 2;
    int wn = warp & 3;
    int m0 = blockIdx.y * BM;
    int n0 = blockIdx.x * BN;

    int aRow[4], aXor[4];
#pragma unroll
    for (int mt = 0; mt < 4; mt++) {
        int r = wm * 64 + mt * 16 + (lane & 15);
        aRow[mt] = r * 128;
        aXor[mt] = r & 7;
    }
    int aCb = lane >> 4;
    int bRow[4], bXor[4];
#pragma unroll
    for (int ntp = 0; ntp < 4; ntp++) {
        int r = wn * 64 + ntp * 16 + (lane & 7) + ((lane >> 4) << 3);
        bRow[ntp] = r * 128;
        bXor[ntp] = r & 7;
    }
    int bCb = (lane >> 3) & 1;

    float acc[4][8][4];
#pragma unroll
    for (int mt = 0; mt < 4; mt++)
#pragma unroll
        for (int nt = 0; nt < 8; nt++)
#pragma unroll
            for (int q = 0; q < 4; q++) acc[mt][nt][q] = 0.f;

    auto load_stage = [&](int g) {
        int k0 = g * BKH;
        uint32_t sA = base + (g % STAGES) * STG;
        uint32_t sB = sA + ASTG;
#pragma unroll
        for (int j = 0; j < 4; j++) {
            int c = tid + 256 * j;
            int r = c >> 3, q = c & 7;
            int grow = m0 + r; if (grow >= VOCAB) grow = VOCAB - 1;
            uint32_t off = (uint32_t)(r * 128 + ((q ^ (r & 7)) << 4));
            cpa16(sA + off, g_Ah + (size_t)grow * DIM + k0 + q * 8);
        }
#pragma unroll
        for (int j = 0; j < 8; j++) {
            int c = tid + 256 * j;
            int r = c >> 3, q = c & 7;
            uint32_t off = (uint32_t)(r * 128 + ((q ^ (r & 7)) << 4));
            cpa16(sB + off, g_Bh + (size_t)(n0 + r) * DIM + k0 + q * 8);
        }
        cp_commit();
    };

    load_stage(0);
    load_stage(1);

    for (int i = 0; i < NIT; i++) {
        if (i == NIT - 1) cp_wait<0>(); else cp_wait<1>();
        __syncthreads();

        if (i + 2 < NIT) load_stage(i + 2);

        uint32_t sA = base + (i % STAGES) * STG;
        uint32_t sB = sA + ASTG;

        uint32_t a[2][4][4], b[2][8][2];

        auto ldA = [&](int s, int buf) {
#pragma unroll
            for (int mt = 0; mt < 4; mt++) {
                uint32_t addr = sA + aRow[mt] + ((uint32_t)((2 * s + aCb) ^ aXor[mt]) << 4);
                ldsm4(a[buf][mt][0], a[buf][mt][1], a[buf][mt][2], a[buf][mt][3], addr);
            }
        };
        auto ldB = [&](int s, int buf) {
#pragma unroll
            for (int ntp = 0; ntp < 4; ntp++) {
                uint32_t addr = sB + bRow[ntp] + ((uint32_t)((2 * s + bCb) ^ bXor[ntp]) << 4);
                ldsm4(b[buf][2 * ntp][0], b[buf][2 * ntp][1],
                      b[buf][2 * ntp + 1][0], b[buf][2 * ntp + 1][1], addr);
            }
        };

        ldA(0, 0); ldB(0, 0);
#pragma unroll
        for (int s = 0; s < 4; s++) {
            int cur = s & 1;
            if (s < 3) { ldA(s + 1, cur ^ 1); ldB(s + 1, cur ^ 1); }
#pragma unroll
            for (int mt = 0; mt < 4; mt++)
#pragma unroll
                for (int nt = 0; nt < 8; nt++)
                    mma16816(acc[mt][nt], a[cur][mt], b[cur][nt]);
        }
        __syncthreads();
    }

    // ---- epilogue: fp16 stores ----
#pragma unroll
    for (int mt = 0; mt < 4; mt++) {
        int r0 = m0 + wm * 64 + mt * 16 + (lane >> 2);
        int r1 = r0 + 8;
        __half* p0 = g_proj + (size_t)r0 * NCOL + n0 + wn * 64 + (lane & 3) * 2;
        __half* p1 = g_proj + (size_t)r1 * NCOL + n0 + wn * 64 + (lane & 3) * 2;
        bool ok0 = r0 < VOCAB, ok1 = r1 < VOCAB;
#pragma unroll
        for (int nt = 0; nt < 8; nt++) {
            if (ok0) *reinterpret_cast<__half2*>(p0 + nt * 8) =
                __floats2half2_rn(acc[mt][nt][0], acc[mt][nt][1]);
            if (ok1) *reinterpret_cast<__half2*>(p1 + nt * 8) =
                __floats2half2_rn(acc[mt][nt][2], acc[mt][nt][3]);
        }
    }
}

// ---------------------------------------------------------------------------
// Kernel 4a: zero output (atomicMax accumulation target)
// ---------------------------------------------------------------------------
__global__ void init_out(float* __restrict__ out, int n) {
    int i = blockIdx.x * blockDim.x + threadIdx.x;
    if (i < n) out[i] = 0.f;
}

// ---------------------------------------------------------------------------
// Kernel 4b: pooling, 4-way sequence split, half2 lanes, atomicMax combine
//   block = (seq, quarter); 128 threads; thread t covers features 2t, 2t+1
// ---------------------------------------------------------------------------
__global__ __launch_bounds__(128)
void pool_kernel(const int* __restrict__ text,
                 const float* __restrict__ b3,
                 const float* __restrict__ b4,
                 const float* __restrict__ b5,
                 float* __restrict__ out) {
    int blk = blockIdx.x;
    int seq = blk >> 2;
    int h   = blk & 3;
    int t0  = h * 32;
    int t1  = min(SEQL, t0 + 32 + 4);
    int n   = t1 - t0;
    // exclusive end of window-starts owned by this block, per K
    int e3 = min(t0 + 32, SEQL - 2);
    int e4 = min(t0 + 32, SEQL - 3);
    int e5 = min(t0 + 32, SEQL - 4);

    __shared__ int s_tok[36];
    int ft = threadIdx.x;                 // 0..127 -> features 2ft, 2ft+1
    if (ft < n) s_tok[ft] = text[seq * SEQL + t0 + ft];
    __syncthreads();

    float2 m3 = make_float2(-1e30f, -1e30f), m4 = m3, m5 = m3;
    float2 z  = make_float2(0.f, 0.f);
    float2 c3a = z, c3b = z;
    float2 c4a = z, c4b = z, c4c = z;
    float2 c5a = z, c5b = z, c5c = z, c5d = z;

    for (int j = 0; j < n; j++) {
        const __half2* row =
            reinterpret_cast<const __half2*>(g_proj + (size_t)s_tok[j] * NCOL) + ft;
        float2 t0v  = __half22float2(row[0 * 128]);
        float2 t1v  = __half22float2(row[1 * 128]);
        float2 t2v  = __half22float2(row[2 * 128]);
        float2 t3v  = __half22float2(row[3 * 128]);
        float2 t4v  = __half22float2(row[4 * 128]);
        float2 t5v  = __half22float2(row[5 * 128]);
        float2 t6v  = __half22float2(row[6 * 128]);
        float2 t7v  = __half22float2(row[7 * 128]);
        float2 t8v  = __half22float2(row[8 * 128]);
        float2 t9v  = __half22float2(row[9 * 128]);
        float2 t10v = __half22float2(row[10 * 128]);
        float2 t11v = __half22float2(row[11 * 128]);

        int p = t0 + j;
        if (j >= 2 && (p - 2) < e3) m3 = max2(m3, add2(c3b, t2v));
        c3b = add2(c3a, t1v);  c3a = t0v;
        if (j >= 3 && (p - 3) < e4) m4 = max2(m4, add2(c4c, t6v));
        c4c = add2(c4b, t5v);  c4b = add2(c4a, t4v);  c4a = t3v;
        if (j >= 4 && (p - 4) < e5) m5 = max2(m5, add2(c5d, t11v));
        c5d = add2(c5c, t10v); c5c = add2(c5b, t9v);  c5b = add2(c5a, t8v);  c5a = t7v;
    }

    float2 bb3 = *reinterpret_cast<const float2*>(b3 + 2 * ft);
    float2 bb4 = *reinterpret_cast<const float2*>(b4 + 2 * ft);
    float2 bb5 = *reinterpret_cast<const float2*>(b5 + 2 * ft);

    unsigned int* o = reinterpret_cast<unsigned int*>(out + (size_t)seq * (3 * FEAT));
    atomicMax(&o[2 * ft],            __float_as_uint(fmaxf(m3.x + bb3.x, 0.f)));
    atomicMax(&o[2 * ft + 1],        __float_as_uint(fmaxf(m3.y + bb3.y, 0.f)));
    atomicMax(&o[FEAT + 2 * ft],     __float_as_uint(fmaxf(m4.x + bb4.x, 0.f)));
    atomicMax(&o[FEAT + 2 * ft + 1], __float_as_uint(fmaxf(m4.y + bb4.y, 0.f)));
    atomicMax(&o[2 * FEAT + 2 * ft],     __float_as_uint(fmaxf(m5.x + bb5.x, 0.f)));
    atomicMax(&o[2 * FEAT + 2 * ft + 1], __float_as_uint(fmaxf(m5.y + bb5.y, 0.f)));
}

// ---------------------------------------------------------------------------
extern "C" void kernel_launch(void* const* d_in, const int* in_sizes, int n_in,
                              void* d_out, int out_size) {
    const int*   text  = (const int*)  d_in[0];
    const float* embed = (const float*)d_in[1];
    const float* w3    = (const float*)d_in[2];
    const float* b3    = (const float*)d_in[3];
    const float* w4    = (const float*)d_in[4];
    const float* b4    = (const float*)d_in[5];
    const float* w5    = (const float*)d_in[6];
    const float* b5    = (const float*)d_in[7];
    float* out = (float*)d_out;

    convert_embed<<<(VOCAB * DIM / 8 + 255) / 256, 256>>>(embed);
    pack_w<<<(NCOL * DIM + 255) / 256, 256>>>(w3, w4, w5);
    init_out<<<(out_size + 1023) / 1024, 1024>>>(out, out_size);

    cudaFuncSetAttribute(gemm_f16, cudaFuncAttributeMaxDynamicSharedMemorySize, GEMM_SMEM);
    gemm_f16<<<dim3(NCOL / BN, (VOCAB + BM - 1) / BM), 256, GEMM_SMEM>>>();

    pool_kernel<<<NSEQ * 4, 128>>>(text, b3, b4, b5, out);
}

// round 7
// speedup vs baseline: 5.6259x; 1.0300x over previous
#include <cuda_runtime.h>
#include <cuda_fp16.h>
#include <stdint.h>

// ---------------------------------------------------------------------------
#define VOCAB 30000
#define DIM   512
#define FEAT  256
#define SEQL  128
#define NSEQ  1024
#define NCOL  3072

__device__ __align__(128) __half g_Ah[(size_t)VOCAB * DIM];
__device__ __align__(128) __half g_Bh[(size_t)NCOL * DIM];
__device__ __align__(128) __half g_proj[(size_t)VOCAB * NCOL];

// ---------------------------------------------------------------------------
static __device__ __forceinline__ uint32_t smem_u32(const void* p) {
    uint32_t a;
    asm("{ .reg .u64 t; cvta.to.shared.u64 t, %1; cvt.u32.u64 %0, t; }" : "=r"(a) : "l"(p));
    return a;
}
static __device__ __forceinline__ void cpa16(uint32_t s, const void* g) {
    asm volatile("cp.async.cg.shared.global [%0], [%1], 16;" :: "r"(s), "l"(g));
}
static __device__ __forceinline__ void cp_commit() {
    asm volatile("cp.async.commit_group;" ::: "memory");
}
template <int N> static __device__ __forceinline__ void cp_wait() {
    asm volatile("cp.async.wait_group %0;" :: "n"(N) : "memory");
}
static __device__ __forceinline__ void ldsm4(uint32_t& r0, uint32_t& r1,
                                             uint32_t& r2, uint32_t& r3, uint32_t a) {
    asm volatile("ldmatrix.sync.aligned.m8n8.x4.shared.b16 {%0,%1,%2,%3}, [%4];"
                 : "=r"(r0), "=r"(r1), "=r"(r2), "=r"(r3) : "r"(a));
}
static __device__ __forceinline__ void mma16816(float* d, const uint32_t* a,
                                                const uint32_t* b) {
    asm volatile(
        "mma.sync.aligned.m16n8k16.row.col.f32.f16.f16.f32 "
        "{%0,%1,%2,%3}, {%4,%5,%6,%7}, {%8,%9}, {%0,%1,%2,%3};"
        : "+f"(d[0]), "+f"(d[1]), "+f"(d[2]), "+f"(d[3])
        : "r"(a[0]), "r"(a[1]), "r"(a[2]), "r"(a[3]), "r"(b[0]), "r"(b[1]));
}
static __device__ __forceinline__ float2 add2(float2 a, float2 b) {
    return make_float2(a.x + b.x, a.y + b.y);
}
static __device__ __forceinline__ float2 max2(float2 a, float2 b) {
    return make_float2(fmaxf(a.x, b.x), fmaxf(a.y, b.y));
}

// ---------------------------------------------------------------------------
// Kernel 1: embed fp32 -> fp16
// ---------------------------------------------------------------------------
__global__ void convert_embed(const float* __restrict__ e) {
    size_t i = ((size_t)blockIdx.x * blockDim.x + threadIdx.x) * 8;
    if (i >= (size_t)VOCAB * DIM) return;
    float4 v0 = *reinterpret_cast<const float4*>(e + i);
    float4 v1 = *reinterpret_cast<const float4*>(e + i + 4);
    __align__(16) __half h[8];
    h[0] = __float2half_rn(v0.x); h[1] = __float2half_rn(v0.y);
    h[2] = __float2half_rn(v0.z); h[3] = __float2half_rn(v0.w);
    h[4] = __float2half_rn(v1.x); h[5] = __float2half_rn(v1.y);
    h[6] = __float2half_rn(v1.z); h[7] = __float2half_rn(v1.w);
    *reinterpret_cast<uint4*>(&g_Ah[i]) = *reinterpret_cast<uint4*>(h);
}

// ---------------------------------------------------------------------------
// Kernel 2: pack weights B[n][k], n = tap*256+f
// ---------------------------------------------------------------------------
__global__ void pack_w(const float* __restrict__ w3,
                       const float* __restrict__ w4,
                       const float* __restrict__ w5) {
    int idx = blockIdx.x * blockDim.x + threadIdx.x;
    if (idx >= NCOL * DIM) return;
    int n = idx >> 9;
    int k = idx & 511;
    int tap = n >> 8;
    int f   = n & 255;
    float v;
    if (tap < 3)      v = w3[(f * DIM + k) * 3 + tap];
    else if (tap < 7) v = w4[(f * DIM + k) * 4 + (tap - 3)];
    else              v = w5[(f * DIM + k) * 5 + (tap - 7)];
    g_Bh[idx] = __float2half_rn(v);
}

// ---------------------------------------------------------------------------
// Kernel 3: fp16 mma.sync GEMM, K=512
//   4-stage cp.async pipeline, ONE barrier per K-iteration, frag double-buffer
// ---------------------------------------------------------------------------
#define BM 128
#define BN 256
#define BKH 64
#define STAGES 4
#define ASTG 16384
#define BSTG 32768
#define STG (ASTG + BSTG)          // 48KB / stage
#define NIT 8
#define GEMM_SMEM (STAGES * STG + 1024)

__global__ __launch_bounds__(256, 1) void gemm_f16() {
    extern __shared__ char dyn[];
    uint32_t base = (smem_u32(dyn) + 1023) & ~1023u;

    int tid  = threadIdx.x;
    int lane = tid & 31;
    int warp = tid >> 5;
    int wm = warp >> 2;
    int wn = warp & 3;
    int m0 = blockIdx.y * BM;
    int n0 = blockIdx.x * BN;

    int aRow[4], aXor[4];
#pragma unroll
    for (int mt = 0; mt < 4; mt++) {
        int r = wm * 64 + mt * 16 + (lane & 15);
        aRow[mt] = r * 128;
        aXor[mt] = r & 7;
    }
    int aCb = lane >> 4;
    int bRow[4], bXor[4];
#pragma unroll
    for (int ntp = 0; ntp < 4; ntp++) {
        int r = wn * 64 + ntp * 16 + (lane & 7) + ((lane >> 4) << 3);
        bRow[ntp] = r * 128;
        bXor[ntp] = r & 7;
    }
    int bCb = (lane >> 3) & 1;

    float acc[4][8][4];
#pragma unroll
    for (int mt = 0; mt < 4; mt++)
#pragma unroll
        for (int nt = 0; nt < 8; nt++)
#pragma unroll
            for (int q = 0; q < 4; q++) acc[mt][nt][q] = 0.f;

    auto load_stage = [&](int g) {
        int k0 = g * BKH;
        uint32_t sA = base + (g % STAGES) * STG;
        uint32_t sB = sA + ASTG;
#pragma unroll
        for (int j = 0; j < 4; j++) {
            int c = tid + 256 * j;
            int r = c >> 3, q = c & 7;
            int grow = m0 + r; if (grow >= VOCAB) grow = VOCAB - 1;
            uint32_t off = (uint32_t)(r * 128 + ((q ^ (r & 7)) << 4));
            cpa16(sA + off, g_Ah + (size_t)grow * DIM + k0 + q * 8);
        }
#pragma unroll
        for (int j = 0; j < 8; j++) {
            int c = tid + 256 * j;
            int r = c >> 3, q = c & 7;
            uint32_t off = (uint32_t)(r * 128 + ((q ^ (r & 7)) << 4));
            cpa16(sB + off, g_Bh + (size_t)(n0 + r) * DIM + k0 + q * 8);
        }
        cp_commit();
    };

    load_stage(0);
    load_stage(1);
    load_stage(2);

    for (int i = 0; i < NIT; i++) {
        // stages committed so far: min(i+3, NIT). Need stage i complete.
        if (i < NIT - 2)      cp_wait<2>();
        else if (i == NIT - 2) cp_wait<1>();
        else                   cp_wait<0>();
        __syncthreads();   // single barrier per iter: bounds skew; buffer (i+3)%4
                           // was read in iter i-1, all warps past it now.

        if (i + 3 < NIT) load_stage(i + 3);

        uint32_t sA = base + (i % STAGES) * STG;
        uint32_t sB = sA + ASTG;

        uint32_t a[2][4][4], b[2][8][2];

        auto ldA = [&](int s, int buf) {
#pragma unroll
            for (int mt = 0; mt < 4; mt++) {
                uint32_t addr = sA + aRow[mt] + ((uint32_t)((2 * s + aCb) ^ aXor[mt]) << 4);
                ldsm4(a[buf][mt][0], a[buf][mt][1], a[buf][mt][2], a[buf][mt][3], addr);
            }
        };
        auto ldB = [&](int s, int buf) {
#pragma unroll
            for (int ntp = 0; ntp < 4; ntp++) {
                uint32_t addr = sB + bRow[ntp] + ((uint32_t)((2 * s + bCb) ^ bXor[ntp]) << 4);
                ldsm4(b[buf][2 * ntp][0], b[buf][2 * ntp][1],
                      b[buf][2 * ntp + 1][0], b[buf][2 * ntp + 1][1], addr);
            }
        };

        ldA(0, 0); ldB(0, 0);
#pragma unroll
        for (int s = 0; s < 4; s++) {
            int cur = s & 1;
            if (s < 3) { ldA(s + 1, cur ^ 1); ldB(s + 1, cur ^ 1); }
#pragma unroll
            for (int mt = 0; mt < 4; mt++)
#pragma unroll
                for (int nt = 0; nt < 8; nt++)
                    mma16816(acc[mt][nt], a[cur][mt], b[cur][nt]);
        }
        // no trailing barrier: next iteration's top barrier suffices
    }

    // ---- epilogue: fp16 stores ----
#pragma unroll
    for (int mt = 0; mt < 4; mt++) {
        int r0 = m0 + wm * 64 + mt * 16 + (lane >> 2);
        int r1 = r0 + 8;
        __half* p0 = g_proj + (size_t)r0 * NCOL + n0 + wn * 64 + (lane & 3) * 2;
        __half* p1 = g_proj + (size_t)r1 * NCOL + n0 + wn * 64 + (lane & 3) * 2;
        bool ok0 = r0 < VOCAB, ok1 = r1 < VOCAB;
#pragma unroll
        for (int nt = 0; nt < 8; nt++) {
            if (ok0) *reinterpret_cast<__half2*>(p0 + nt * 8) =
                __floats2half2_rn(acc[mt][nt][0], acc[mt][nt][1]);
            if (ok1) *reinterpret_cast<__half2*>(p1 + nt * 8) =
                __floats2half2_rn(acc[mt][nt][2], acc[mt][nt][3]);
        }
    }
}

// ---------------------------------------------------------------------------
// Kernel 4a: zero output (atomicMax accumulation target)
// ---------------------------------------------------------------------------
__global__ void init_out(float* __restrict__ out, int n) {
    int i = blockIdx.x * blockDim.x + threadIdx.x;
    if (i < n) out[i] = 0.f;
}

// ---------------------------------------------------------------------------
// Kernel 4b: pooling, 4-way sequence split, half2 lanes, atomicMax combine
// ---------------------------------------------------------------------------
__global__ __launch_bounds__(128)
void pool_kernel(const int* __restrict__ text,
                 const float* __restrict__ b3,
                 const float* __restrict__ b4,
                 const float* __restrict__ b5,
                 float* __restrict__ out) {
    int blk = blockIdx.x;
    int seq = blk >> 2;
    int h   = blk & 3;
    int t0  = h * 32;
    int t1  = min(SEQL, t0 + 32 + 4);
    int n   = t1 - t0;
    int e3 = min(t0 + 32, SEQL - 2);
    int e4 = min(t0 + 32, SEQL - 3);
    int e5 = min(t0 + 32, SEQL - 4);

    __shared__ int s_tok[36];
    int ft = threadIdx.x;
    if (ft < n) s_tok[ft] = text[seq * SEQL + t0 + ft];
    __syncthreads();

    float2 m3 = make_float2(-1e30f, -1e30f), m4 = m3, m5 = m3;
    float2 z  = make_float2(0.f, 0.f);
    float2 c3a = z, c3b = z;
    float2 c4a = z, c4b = z, c4c = z;
    float2 c5a = z, c5b = z, c5c = z, c5d = z;

    for (int j = 0; j < n; j++) {
        const __half2* row =
            reinterpret_cast<const __half2*>(g_proj + (size_t)s_tok[j] * NCOL) + ft;
        float2 t0v  = __half22float2(row[0 * 128]);
        float2 t1v  = __half22float2(row[1 * 128]);
        float2 t2v  = __half22float2(row[2 * 128]);
        float2 t3v  = __half22float2(row[3 * 128]);
        float2 t4v  = __half22float2(row[4 * 128]);
        float2 t5v  = __half22float2(row[5 * 128]);
        float2 t6v  = __half22float2(row[6 * 128]);
        float2 t7v  = __half22float2(row[7 * 128]);
        float2 t8v  = __half22float2(row[8 * 128]);
        float2 t9v  = __half22float2(row[9 * 128]);
        float2 t10v = __half22float2(row[10 * 128]);
        float2 t11v = __half22float2(row[11 * 128]);

        int p = t0 + j;
        if (j >= 2 && (p - 2) < e3) m3 = max2(m3, add2(c3b, t2v));
        c3b = add2(c3a, t1v);  c3a = t0v;
        if (j >= 3 && (p - 3) < e4) m4 = max2(m4, add2(c4c, t6v));
        c4c = add2(c4b, t5v);  c4b = add2(c4a, t4v);  c4a = t3v;
        if (j >= 4 && (p - 4) < e5) m5 = max2(m5, add2(c5d, t11v));
        c5d = add2(c5c, t10v); c5c = add2(c5b, t9v);  c5b = add2(c5a, t8v);  c5a = t7v;
    }

    float2 bb3 = *reinterpret_cast<const float2*>(b3 + 2 * ft);
    float2 bb4 = *reinterpret_cast<const float2*>(b4 + 2 * ft);
    float2 bb5 = *reinterpret_cast<const float2*>(b5 + 2 * ft);

    unsigned int* o = reinterpret_cast<unsigned int*>(out + (size_t)seq * (3 * FEAT));
    atomicMax(&o[2 * ft],            __float_as_uint(fmaxf(m3.x + bb3.x, 0.f)));
    atomicMax(&o[2 * ft + 1],        __float_as_uint(fmaxf(m3.y + bb3.y, 0.f)));
    atomicMax(&o[FEAT + 2 * ft],     __float_as_uint(fmaxf(m4.x + bb4.x, 0.f)));
    atomicMax(&o[FEAT + 2 * ft + 1], __float_as_uint(fmaxf(m4.y + bb4.y, 0.f)));
    atomicMax(&o[2 * FEAT + 2 * ft],     __float_as_uint(fmaxf(m5.x + bb5.x, 0.f)));
    atomicMax(&o[2 * FEAT + 2 * ft + 1], __float_as_uint(fmaxf(m5.y + bb5.y, 0.f)));
}

// ---------------------------------------------------------------------------
extern "C" void kernel_launch(void* const* d_in, const int* in_sizes, int n_in,
                              void* d_out, int out_size) {
    const int*   text  = (const int*)  d_in[0];
    const float* embed = (const float*)d_in[1];
    const float* w3    = (const float*)d_in[2];
    const float* b3    = (const float*)d_in[3];
    const float* w4    = (const float*)d_in[4];
    const float* b4    = (const float*)d_in[5];
    const float* w5    = (const float*)d_in[6];
    const float* b5    = (const float*)d_in[7];
    float* out = (float*)d_out;

    convert_embed<<<(VOCAB * DIM / 8 + 255) / 256, 256>>>(embed);
    pack_w<<<(NCOL * DIM + 255) / 256, 256>>>(w3, w4, w5);
    init_out<<<(out_size + 1023) / 1024, 1024>>>(out, out_size);

    cudaFuncSetAttribute(gemm_f16, cudaFuncAttributeMaxDynamicSharedMemorySize, GEMM_SMEM);
    gemm_f16<<<dim3(NCOL / BN, (VOCAB + BM - 1) / BM), 256, GEMM_SMEM>>>();

    pool_kernel<<<NSEQ * 4, 128>>>(text, b3, b4, b5, out);
}